// round 8
// baseline (speedup 1.0000x reference)
#include <cuda_runtime.h>
#include <math.h>

#define T_LEN 8192
#define THREADS_SCAN 1024
#define NWARPS (THREADS_SCAN / 32)       // 32
#define PER (T_LEN / THREADS_SCAN)       // 8 elements per thread
#define DISCOUNT 0.99f
#define EPS 1e-9f
#define MAX_ROWS 4096                    // B = 4096 in this problem

__device__ float g_rowsum[MAX_ROWS];
__device__ float g_rowinv[MAX_ROWS];
__device__ float g_mean;
// Inter-pass state: per-WARP incoming carry (0.5 MB) + packed per-thread
// done masks, 4 x 8-bit masks per uint32 (4 MB).
__device__ float    g_wcarry[MAX_ROWS * NWARPS];
__device__ unsigned g_mask32[MAX_ROWS * THREADS_SCAN / 4];

// ---------------------------------------------------------------------------
// P1: per-row reverse affine scan -> per-warp carry + per-row stats.
// ret[t] = r[t] + g[t]*ret[t+1],  g[t] = DISCOUNT*(1-done[t]), done binary.
// All input reads .cs (streaming; L2 retention across passes measured as a
// loss in R7).
// ---------------------------------------------------------------------------
__global__ __launch_bounds__(THREADS_SCAN, 2)
void scan_stats_kernel(const float* __restrict__ rew,
                       const float* __restrict__ done)
{
    const int b = blockIdx.x;
    const size_t rowoff = (size_t)b * T_LEN;
    const float* r = rew + rowoff;
    const float* d = done + rowoff;

    const int j    = threadIdx.x;
    const int lane = j & 31;
    const int warp = j >> 5;
    const int tbase = T_LEN - PER * (j + 1);

    float rv[PER];
    unsigned mask = 0;   // bit i set -> done at local index i

#pragma unroll
    for (int k = 0; k < PER / 4; k++) {
        float4 rr = __ldcs((const float4*)(r + tbase) + k);
        float4 dd = __ldcs((const float4*)(d + tbase) + k);
        rv[4 * k + 0] = rr.x;
        rv[4 * k + 1] = rr.y;
        rv[4 * k + 2] = rr.z;
        rv[4 * k + 3] = rr.w;
        if (dd.x != 0.0f) mask |= (1u << (4 * k + 0));
        if (dd.y != 0.0f) mask |= (1u << (4 * k + 1));
        if (dd.z != 0.0f) mask |= (1u << (4 * k + 2));
        if (dd.w != 0.0f) mask |= (1u << (4 * k + 3));
    }

    // Compose this thread's affine map y_out = A*y_in + B (t-descending):
    //   done:  A' = 0,       B' = r_i
    //   else:  A' = 0.99*A,  B' = 0.99*B + r_i
    float A = 1.0f, B = 0.0f;
#pragma unroll
    for (int i = PER - 1; i >= 0; i--) {
        const bool dn = (mask >> i) & 1u;
        B = dn ? rv[i] : fmaf(DISCOUNT, B, rv[i]);
        A = dn ? 0.0f  : DISCOUNT * A;
    }

    // Intra-warp inclusive affine scan (5 shfl steps) — P2 replays this
    // exact sequence, so it must stay bitwise-stable.
#pragma unroll
    for (int off = 1; off < 32; off <<= 1) {
        float a1 = __shfl_up_sync(0xffffffffu, A, off);
        float b1 = __shfl_up_sync(0xffffffffu, B, off);
        if (lane >= off) {
            B = fmaf(A, b1, B);
            A = A * a1;
        }
    }

    // Exclusive-within-warp map for this thread
    float Ae = __shfl_up_sync(0xffffffffu, A, 1);
    float Be = __shfl_up_sync(0xffffffffu, B, 1);
    if (lane == 0) { Ae = 1.0f; Be = 0.0f; }

    __shared__ float sWA[NWARPS];
    __shared__ float sWB[NWARPS];
    __shared__ float sWP[NWARPS];
    __shared__ float sRS[NWARPS];
    __shared__ float sRQ[NWARPS];

    if (lane == 31) { sWA[warp] = A; sWB[warp] = B; }
    __syncthreads();

    if (warp == 0) {
        float a  = sWA[lane];
        float bb = sWB[lane];
#pragma unroll
        for (int off = 1; off < 32; off <<= 1) {
            float a1 = __shfl_up_sync(0xffffffffu, a, off);
            float b1 = __shfl_up_sync(0xffffffffu, bb, off);
            if (lane >= off) {
                bb = fmaf(a, b1, bb);
                a = a * a1;
            }
        }
        sWP[lane] = bb;
    }
    __syncthreads();

    // Warp-incoming value (row starts from y0 = 0): uniform per warp.
    const float Bw = (warp == 0) ? 0.0f : sWP[warp - 1];
    if (lane == 0) g_wcarry[b * NWARPS + warp] = Bw;

    // Pack 4 lanes' 8-bit masks into one uint32; every 4th lane stores.
    {
        unsigned m1 = __shfl_down_sync(0xffffffffu, mask, 1);
        unsigned m2 = __shfl_down_sync(0xffffffffu, mask, 2);
        unsigned m3 = __shfl_down_sync(0xffffffffu, mask, 3);
        if ((lane & 3) == 0) {
            const size_t widx = ((size_t)b * THREADS_SCAN + j) >> 2;
            g_mask32[widx] = mask | (m1 << 8) | (m2 << 16) | (m3 << 24);
        }
    }

    // This thread's incoming value; rematerialize for stats (same fma order
    // as P2 replay -> bitwise identical).
    float y = fmaf(Ae, Bw, Be);
    float lsum = 0.0f, lsq = 0.0f;
#pragma unroll
    for (int i = PER - 1; i >= 0; i--) {
        const bool dn = (mask >> i) & 1u;
        y = dn ? rv[i] : fmaf(DISCOUNT, y, rv[i]);
        lsum += y;
        lsq  = fmaf(y, y, lsq);
    }

    // Deterministic block reduction of sum / sumsq
#pragma unroll
    for (int off = 16; off > 0; off >>= 1) {
        lsum += __shfl_down_sync(0xffffffffu, lsum, off);
        lsq  += __shfl_down_sync(0xffffffffu, lsq,  off);
    }
    if (lane == 0) { sRS[warp] = lsum; sRQ[warp] = lsq; }
    __syncthreads();
    if (warp == 0) {
        float s = sRS[lane];
        float q = sRQ[lane];
#pragma unroll
        for (int off = 16; off > 0; off >>= 1) {
            s += __shfl_down_sync(0xffffffffu, s, off);
            q += __shfl_down_sync(0xffffffffu, q, off);
        }
        if (lane == 0) {
            g_rowsum[b] = s;
            float var = (q - s * s * (1.0f / T_LEN)) * (1.0f / (T_LEN - 1));
            var = fmaxf(var, 0.0f);
            g_rowinv[b] = 1.0f / (sqrtf(var) + EPS);
        }
    }
}

// ---------------------------------------------------------------------------
// K2: deterministic reduction of row sums -> global mean
// ---------------------------------------------------------------------------
__global__ __launch_bounds__(1024)
void mean_kernel(int n_rows)
{
    __shared__ double sd[1024];
    const int j = threadIdx.x;
    double acc = 0.0;
    for (int i = j; i < n_rows; i += 1024)
        acc += (double)g_rowsum[i];
    sd[j] = acc;
    __syncthreads();
#pragma unroll
    for (int off = 512; off > 0; off >>= 1) {
        if (j < off) sd[j] += sd[j + off];
        __syncthreads();
    }
    if (j == 0)
        g_mean = (float)(sd[0] / ((double)n_rows * (double)T_LEN));
}

// ---------------------------------------------------------------------------
// P2: barrier-free replay + normalize + store. No smem, no __syncthreads.
// Recomputes the warp-level affine scan bitwise-identically from rv + mask,
// adds the stored per-warp carry, normalizes, streams out.
// ---------------------------------------------------------------------------
__global__ __launch_bounds__(THREADS_SCAN, 2)
void finalize_kernel(const float* __restrict__ rew,
                     float* __restrict__ out)
{
    const int b = blockIdx.x;
    const size_t rowoff = (size_t)b * T_LEN;
    const float* r = rew + rowoff;
    float* o = out + rowoff;

    const int j    = threadIdx.x;
    const int lane = j & 31;
    const int warp = j >> 5;
    const int tbase = T_LEN - PER * (j + 1);

    // Unpack this thread's 8-bit mask from the packed word (broadcast load).
    const size_t sidx = (size_t)b * THREADS_SCAN + j;
    const unsigned mword = g_mask32[sidx >> 2];
    const unsigned mask = (mword >> ((j & 3) * 8)) & 0xFFu;

    const float Bw   = g_wcarry[b * NWARPS + warp];
    const float mean = g_mean;
    const float inv  = g_rowinv[b];

    float rv[PER];
#pragma unroll
    for (int k = 0; k < PER / 4; k++) {
        float4 rr = __ldcs((const float4*)(r + tbase) + k);
        rv[4 * k + 0] = rr.x;
        rv[4 * k + 1] = rr.y;
        rv[4 * k + 2] = rr.z;
        rv[4 * k + 3] = rr.w;
    }

    // Recompose this thread's affine map (identical ops to P1)
    float A = 1.0f, B = 0.0f;
#pragma unroll
    for (int i = PER - 1; i >= 0; i--) {
        const bool dn = (mask >> i) & 1u;
        B = dn ? rv[i] : fmaf(DISCOUNT, B, rv[i]);
        A = dn ? 0.0f  : DISCOUNT * A;
    }

    // Replay the intra-warp inclusive scan (identical ops to P1)
#pragma unroll
    for (int off = 1; off < 32; off <<= 1) {
        float a1 = __shfl_up_sync(0xffffffffu, A, off);
        float b1 = __shfl_up_sync(0xffffffffu, B, off);
        if (lane >= off) {
            B = fmaf(A, b1, B);
            A = A * a1;
        }
    }
    float Ae = __shfl_up_sync(0xffffffffu, A, 1);
    float Be = __shfl_up_sync(0xffffffffu, B, 1);
    if (lane == 0) { Ae = 1.0f; Be = 0.0f; }

    // This thread's incoming value, then replay + normalize + store.
    float y = fmaf(Ae, Bw, Be);
#pragma unroll
    for (int k = PER / 4 - 1; k >= 0; k--) {
        float4 w;
        {
            const bool dn = (mask >> (4 * k + 3)) & 1u;
            y = dn ? rv[4 * k + 3] : fmaf(DISCOUNT, y, rv[4 * k + 3]);
            w.w = (y - mean) * inv;
        }
        {
            const bool dn = (mask >> (4 * k + 2)) & 1u;
            y = dn ? rv[4 * k + 2] : fmaf(DISCOUNT, y, rv[4 * k + 2]);
            w.z = (y - mean) * inv;
        }
        {
            const bool dn = (mask >> (4 * k + 1)) & 1u;
            y = dn ? rv[4 * k + 1] : fmaf(DISCOUNT, y, rv[4 * k + 1]);
            w.y = (y - mean) * inv;
        }
        {
            const bool dn = (mask >> (4 * k + 0)) & 1u;
            y = dn ? rv[4 * k + 0] : fmaf(DISCOUNT, y, rv[4 * k + 0]);
            w.x = (y - mean) * inv;
        }
        __stcs((float4*)(o + tbase) + k, w);
    }
}

extern "C" void kernel_launch(void* const* d_in, const int* in_sizes, int n_in,
                              void* d_out, int out_size)
{
    const float* rewards = (const float*)d_in[0];
    const float* dones   = (const float*)d_in[1];
    float* out = (float*)d_out;

    const int n = in_sizes[0];
    const int B = n / T_LEN;

    scan_stats_kernel<<<B, THREADS_SCAN>>>(rewards, dones);
    mean_kernel<<<1, 1024>>>(B);
    finalize_kernel<<<B, THREADS_SCAN>>>(rewards, out);
}

// round 9
// speedup vs baseline: 1.0147x; 1.0147x over previous
#include <cuda_runtime.h>
#include <math.h>

#define T_LEN 8192
#define THREADS_SCAN 1024
#define NWARPS (THREADS_SCAN / 32)       // 32
#define PER (T_LEN / THREADS_SCAN)       // 8 elements per thread
#define DISCOUNT 0.99f
#define EPS 1e-9f
#define MAX_ROWS 4096                    // B = 4096 in this problem

__device__ float g_rowsum[MAX_ROWS];
__device__ float g_rowinv[MAX_ROWS];
__device__ float g_mean;
__device__ unsigned g_ticket = 0;        // last-block election; reset each run
// Per-thread replay state: incoming carry + packed done mask (8 bits used)
__device__ float         g_carry[MAX_ROWS * THREADS_SCAN];   // 16 MB
__device__ unsigned char g_mask [MAX_ROWS * THREADS_SCAN];   //  4 MB

// ---------------------------------------------------------------------------
// P1: per-row reverse affine scan -> per-thread carry + per-row stats.
// ret[t] = r[t] + g[t]*ret[t+1],  g[t] = DISCOUNT*(1-done[t]), done binary.
// The LAST block to finish also reduces all row sums to the global mean
// (deterministic double tree), removing a separate kernel launch.
// ---------------------------------------------------------------------------
__global__ __launch_bounds__(THREADS_SCAN, 2)
void scan_stats_kernel(const float* __restrict__ rew,
                       const float* __restrict__ done)
{
    const int b = blockIdx.x;
    const size_t rowoff = (size_t)b * T_LEN;
    const float* r = rew + rowoff;
    const float* d = done + rowoff;

    const int j    = threadIdx.x;
    const int lane = j & 31;
    const int warp = j >> 5;
    const int tbase = T_LEN - PER * (j + 1);

    float rv[PER];
    unsigned mask = 0;   // bit i set -> done at local index i

#pragma unroll
    for (int k = 0; k < PER / 4; k++) {
        float4 rr = __ldcs((const float4*)(r + tbase) + k);
        float4 dd = __ldcs((const float4*)(d + tbase) + k);
        rv[4 * k + 0] = rr.x;
        rv[4 * k + 1] = rr.y;
        rv[4 * k + 2] = rr.z;
        rv[4 * k + 3] = rr.w;
        if (dd.x != 0.0f) mask |= (1u << (4 * k + 0));
        if (dd.y != 0.0f) mask |= (1u << (4 * k + 1));
        if (dd.z != 0.0f) mask |= (1u << (4 * k + 2));
        if (dd.w != 0.0f) mask |= (1u << (4 * k + 3));
    }

    // Compose this thread's affine map y_out = A*y_in + B (t-descending):
    //   done:  A' = 0,       B' = r_i
    //   else:  A' = 0.99*A,  B' = 0.99*B + r_i
    float A = 1.0f, B = 0.0f;
#pragma unroll
    for (int i = PER - 1; i >= 0; i--) {
        const bool dn = (mask >> i) & 1u;
        B = dn ? rv[i] : fmaf(DISCOUNT, B, rv[i]);
        A = dn ? 0.0f  : DISCOUNT * A;
    }

    // Intra-warp inclusive affine scan.
#pragma unroll
    for (int off = 1; off < 32; off <<= 1) {
        float a1 = __shfl_up_sync(0xffffffffu, A, off);
        float b1 = __shfl_up_sync(0xffffffffu, B, off);
        if (lane >= off) {
            B = fmaf(A, b1, B);
            A = A * a1;
        }
    }

    // Exclusive-within-warp map for this thread
    float Ae = __shfl_up_sync(0xffffffffu, A, 1);
    float Be = __shfl_up_sync(0xffffffffu, B, 1);
    if (lane == 0) { Ae = 1.0f; Be = 0.0f; }

    __shared__ float sWA[NWARPS];
    __shared__ float sWB[NWARPS];
    __shared__ float sWP[NWARPS];
    __shared__ float sRS[NWARPS];
    __shared__ float sRQ[NWARPS];

    if (lane == 31) { sWA[warp] = A; sWB[warp] = B; }
    __syncthreads();

    if (warp == 0) {
        float a  = sWA[lane];
        float bb = sWB[lane];
#pragma unroll
        for (int off = 1; off < 32; off <<= 1) {
            float a1 = __shfl_up_sync(0xffffffffu, a, off);
            float b1 = __shfl_up_sync(0xffffffffu, bb, off);
            if (lane >= off) {
                bb = fmaf(a, b1, bb);
                a = a * a1;
            }
        }
        sWP[lane] = bb;
    }
    __syncthreads();

    // Incoming value for this thread (row starts from y0 = 0)
    const float Bw = (warp == 0) ? 0.0f : sWP[warp - 1];
    const float yin = fmaf(Ae, Bw, Be);

    // Persist replay state for P2
    const size_t sidx = (size_t)b * THREADS_SCAN + j;
    g_carry[sidx] = yin;
    g_mask[sidx]  = (unsigned char)mask;

    // Rematerialize for stats only (same fma order as P2 replay)
    float y = yin;
    float lsum = 0.0f, lsq = 0.0f;
#pragma unroll
    for (int i = PER - 1; i >= 0; i--) {
        const bool dn = (mask >> i) & 1u;
        y = dn ? rv[i] : fmaf(DISCOUNT, y, rv[i]);
        lsum += y;
        lsq  = fmaf(y, y, lsq);
    }

    // Deterministic block reduction of sum / sumsq
#pragma unroll
    for (int off = 16; off > 0; off >>= 1) {
        lsum += __shfl_down_sync(0xffffffffu, lsum, off);
        lsq  += __shfl_down_sync(0xffffffffu, lsq,  off);
    }
    if (lane == 0) { sRS[warp] = lsum; sRQ[warp] = lsq; }
    __syncthreads();
    if (warp == 0) {
        float s = sRS[lane];
        float q = sRQ[lane];
#pragma unroll
        for (int off = 16; off > 0; off >>= 1) {
            s += __shfl_down_sync(0xffffffffu, s, off);
            q += __shfl_down_sync(0xffffffffu, q, off);
        }
        if (lane == 0) {
            g_rowsum[b] = s;
            float var = (q - s * s * (1.0f / T_LEN)) * (1.0f / (T_LEN - 1));
            var = fmaxf(var, 0.0f);
            g_rowinv[b] = 1.0f / (sqrtf(var) + EPS);
        }
    }

    // ---- Last-block global mean (replaces separate mean kernel) ----
    __shared__ bool amLast;
    __shared__ double sD[THREADS_SCAN];
    if (j == 0) {
        __threadfence();   // make this block's g_rowsum visible first
        const unsigned ticket = atomicAdd(&g_ticket, 1u);
        amLast = (ticket == gridDim.x - 1);
    }
    __syncthreads();
    if (amLast) {
        const int nrows = gridDim.x;
        double acc = 0.0;
        for (int i = j; i < nrows; i += THREADS_SCAN)
            acc += (double)g_rowsum[i];
        sD[j] = acc;
        __syncthreads();
#pragma unroll
        for (int off = THREADS_SCAN / 2; off > 0; off >>= 1) {
            if (j < off) sD[j] += sD[j + off];
            __syncthreads();
        }
        if (j == 0) {
            g_mean = (float)(sD[0] / ((double)nrows * (double)T_LEN));
            g_ticket = 0;          // reset for next graph replay
            __threadfence();
        }
    }
}

// ---------------------------------------------------------------------------
// P2: barrier-free replay + normalize + store.
// Each thread independently: reload its 8 rewards, carry, mask; replay the
// identical fma chain (bitwise-same returns as the stats pass); write
// (y - mean) * rowinv[b].
// ---------------------------------------------------------------------------
__global__ __launch_bounds__(THREADS_SCAN, 2)
void finalize_kernel(const float* __restrict__ rew,
                     float* __restrict__ out)
{
    const int b = blockIdx.x;
    const size_t rowoff = (size_t)b * T_LEN;
    const float* r = rew + rowoff;
    float* o = out + rowoff;

    const int j = threadIdx.x;
    const int tbase = T_LEN - PER * (j + 1);

    const size_t sidx = (size_t)b * THREADS_SCAN + j;
    float y = g_carry[sidx];
    const unsigned mask = g_mask[sidx];
    const float mean = g_mean;
    const float inv  = g_rowinv[b];

    float rv[PER];
#pragma unroll
    for (int k = 0; k < PER / 4; k++) {
        float4 rr = __ldcs((const float4*)(r + tbase) + k);
        rv[4 * k + 0] = rr.x;
        rv[4 * k + 1] = rr.y;
        rv[4 * k + 2] = rr.z;
        rv[4 * k + 3] = rr.w;
    }

#pragma unroll
    for (int k = PER / 4 - 1; k >= 0; k--) {
        float4 w;
        {
            const bool dn = (mask >> (4 * k + 3)) & 1u;
            y = dn ? rv[4 * k + 3] : fmaf(DISCOUNT, y, rv[4 * k + 3]);
            w.w = (y - mean) * inv;
        }
        {
            const bool dn = (mask >> (4 * k + 2)) & 1u;
            y = dn ? rv[4 * k + 2] : fmaf(DISCOUNT, y, rv[4 * k + 2]);
            w.z = (y - mean) * inv;
        }
        {
            const bool dn = (mask >> (4 * k + 1)) & 1u;
            y = dn ? rv[4 * k + 1] : fmaf(DISCOUNT, y, rv[4 * k + 1]);
            w.y = (y - mean) * inv;
        }
        {
            const bool dn = (mask >> (4 * k + 0)) & 1u;
            y = dn ? rv[4 * k + 0] : fmaf(DISCOUNT, y, rv[4 * k + 0]);
            w.x = (y - mean) * inv;
        }
        __stcs((float4*)(o + tbase) + k, w);
    }
}

extern "C" void kernel_launch(void* const* d_in, const int* in_sizes, int n_in,
                              void* d_out, int out_size)
{
    const float* rewards = (const float*)d_in[0];
    const float* dones   = (const float*)d_in[1];
    float* out = (float*)d_out;

    const int n = in_sizes[0];
    const int B = n / T_LEN;

    scan_stats_kernel<<<B, THREADS_SCAN>>>(rewards, dones);
    finalize_kernel<<<B, THREADS_SCAN>>>(rewards, out);
}

// round 11
// speedup vs baseline: 1.1226x; 1.1063x over previous
#include <cuda_runtime.h>
#include <math.h>

#define T_LEN 8192
#define THREADS_SCAN 1024
#define NWARPS (THREADS_SCAN / 32)       // 32
#define PER (T_LEN / THREADS_SCAN)       // 8 elements per thread
#define DISCOUNT_BITS 0x3F7D70A4u        // 0.99f
#define EPS 1e-9f
#define MAX_ROWS 4096                    // B = 4096 in this problem

__device__ float g_rowsum[MAX_ROWS];
__device__ float g_rowinv[MAX_ROWS];
__device__ float g_mean;
// Per-thread replay state: incoming carry + packed done mask (8 bits used)
__device__ float         g_carry[MAX_ROWS * THREADS_SCAN];   // 16 MB
__device__ unsigned char g_mask [MAX_ROWS * THREADS_SCAN];   //  4 MB

// Branchless coefficient: a_i = done_i ? 0.0f : 0.99f, no predicates.
// t = all-ones iff bit i of mask is set; a = bits(0.99) & ~t.
__device__ __forceinline__ float coeff(unsigned mask, int i)
{
    const unsigned t = (unsigned)(((int)(mask << (31 - i))) >> 31);
    return __uint_as_float(DISCOUNT_BITS & ~t);
}

// ---------------------------------------------------------------------------
// P1: per-row reverse affine scan -> per-thread carry + per-row stats.
// ret[t] = r[t] + a[t]*ret[t+1],  a[t] = 0.99*(1-done[t]), done binary.
// ---------------------------------------------------------------------------
__global__ __launch_bounds__(THREADS_SCAN, 2)
void scan_stats_kernel(const float* __restrict__ rew,
                       const float* __restrict__ done)
{
    const int b = blockIdx.x;
    const size_t rowoff = (size_t)b * T_LEN;
    const float* r = rew + rowoff;
    const float* d = done + rowoff;

    const int j    = threadIdx.x;
    const int lane = j & 31;
    const int warp = j >> 5;
    const int tbase = T_LEN - PER * (j + 1);

    float rv[PER];
    unsigned mask = 0;   // bit i set -> done at local index i

#pragma unroll
    for (int k = 0; k < PER / 4; k++) {
        float4 rr = __ldcs((const float4*)(r + tbase) + k);
        float4 dd = __ldcs((const float4*)(d + tbase) + k);
        rv[4 * k + 0] = rr.x;
        rv[4 * k + 1] = rr.y;
        rv[4 * k + 2] = rr.z;
        rv[4 * k + 3] = rr.w;
        if (dd.x != 0.0f) mask |= (1u << (4 * k + 0));
        if (dd.y != 0.0f) mask |= (1u << (4 * k + 1));
        if (dd.z != 0.0f) mask |= (1u << (4 * k + 2));
        if (dd.w != 0.0f) mask |= (1u << (4 * k + 3));
    }

    // Compose this thread's affine map y_out = A*y_in + B (t-descending):
    //   B = a*B + r ; A = a*A   with a in {0, 0.99} (branchless).
    float A = 1.0f, B = 0.0f;
#pragma unroll
    for (int i = PER - 1; i >= 0; i--) {
        const float a = coeff(mask, i);
        B = fmaf(a, B, rv[i]);
        A = a * A;
    }

    // Intra-warp inclusive affine scan.
#pragma unroll
    for (int off = 1; off < 32; off <<= 1) {
        float a1 = __shfl_up_sync(0xffffffffu, A, off);
        float b1 = __shfl_up_sync(0xffffffffu, B, off);
        if (lane >= off) {
            B = fmaf(A, b1, B);
            A = A * a1;
        }
    }

    // Exclusive-within-warp map for this thread
    float Ae = __shfl_up_sync(0xffffffffu, A, 1);
    float Be = __shfl_up_sync(0xffffffffu, B, 1);
    if (lane == 0) { Ae = 1.0f; Be = 0.0f; }

    __shared__ float sWA[NWARPS];
    __shared__ float sWB[NWARPS];
    __shared__ float sWP[NWARPS];
    __shared__ float sRS[NWARPS];
    __shared__ float sRQ[NWARPS];

    if (lane == 31) { sWA[warp] = A; sWB[warp] = B; }
    __syncthreads();

    if (warp == 0) {
        float a  = sWA[lane];
        float bb = sWB[lane];
#pragma unroll
        for (int off = 1; off < 32; off <<= 1) {
            float a1 = __shfl_up_sync(0xffffffffu, a, off);
            float b1 = __shfl_up_sync(0xffffffffu, bb, off);
            if (lane >= off) {
                bb = fmaf(a, b1, bb);
                a = a * a1;
            }
        }
        sWP[lane] = bb;
    }
    __syncthreads();

    // Incoming value for this thread (row starts from y0 = 0)
    const float Bw = (warp == 0) ? 0.0f : sWP[warp - 1];
    const float yin = fmaf(Ae, Bw, Be);

    // Persist replay state for P2
    const size_t sidx = (size_t)b * THREADS_SCAN + j;
    g_carry[sidx] = yin;
    g_mask[sidx]  = (unsigned char)mask;

    // Rematerialize for stats only (EXACT same op sequence as P2 replay)
    float y = yin;
    float lsum = 0.0f, lsq = 0.0f;
#pragma unroll
    for (int i = PER - 1; i >= 0; i--) {
        const float a = coeff(mask, i);
        y = fmaf(a, y, rv[i]);
        lsum += y;
        lsq  = fmaf(y, y, lsq);
    }

    // Deterministic block reduction of sum / sumsq
#pragma unroll
    for (int off = 16; off > 0; off >>= 1) {
        lsum += __shfl_down_sync(0xffffffffu, lsum, off);
        lsq  += __shfl_down_sync(0xffffffffu, lsq,  off);
    }
    if (lane == 0) { sRS[warp] = lsum; sRQ[warp] = lsq; }
    __syncthreads();
    if (warp == 0) {
        float s = sRS[lane];
        float q = sRQ[lane];
#pragma unroll
        for (int off = 16; off > 0; off >>= 1) {
            s += __shfl_down_sync(0xffffffffu, s, off);
            q += __shfl_down_sync(0xffffffffu, q, off);
        }
        if (lane == 0) {
            g_rowsum[b] = s;
            float var = (q - s * s * (1.0f / T_LEN)) * (1.0f / (T_LEN - 1));
            var = fmaxf(var, 0.0f);
            g_rowinv[b] = 1.0f / (sqrtf(var) + EPS);
        }
    }
}

// ---------------------------------------------------------------------------
// K2: deterministic reduction of row sums -> global mean (256 thr, shuffle)
// ---------------------------------------------------------------------------
__global__ __launch_bounds__(256)
void mean_kernel(int n_rows)
{
    __shared__ double sd[8];
    const int j = threadIdx.x;
    const int lane = j & 31;
    const int warp = j >> 5;
    double acc = 0.0;
    for (int i = j; i < n_rows; i += 256)
        acc += (double)g_rowsum[i];
#pragma unroll
    for (int off = 16; off > 0; off >>= 1)
        acc += __shfl_down_sync(0xffffffffu, acc, off);
    if (lane == 0) sd[warp] = acc;
    __syncthreads();
    if (warp == 0) {
        double v = (lane < 8) ? sd[lane] : 0.0;
#pragma unroll
        for (int off = 4; off > 0; off >>= 1)
            v += __shfl_down_sync(0xffffffffu, v, off);
        if (lane == 0)
            g_mean = (float)(v / ((double)n_rows * (double)T_LEN));
    }
}

// ---------------------------------------------------------------------------
// P2: barrier-free replay + normalize + store.
// Reload rewards, carry, mask; replay the IDENTICAL fma chain (bitwise-same
// returns as P1's stats pass); write (y - mean) * rowinv[b].
// ---------------------------------------------------------------------------
__global__ __launch_bounds__(THREADS_SCAN, 2)
void finalize_kernel(const float* __restrict__ rew,
                     float* __restrict__ out)
{
    const int b = blockIdx.x;
    const size_t rowoff = (size_t)b * T_LEN;
    const float* r = rew + rowoff;
    float* o = out + rowoff;

    const int j = threadIdx.x;
    const int tbase = T_LEN - PER * (j + 1);

    const size_t sidx = (size_t)b * THREADS_SCAN + j;
    float y = g_carry[sidx];
    const unsigned mask = g_mask[sidx];
    const float mean = g_mean;
    const float inv  = g_rowinv[b];

    float rv[PER];
#pragma unroll
    for (int k = 0; k < PER / 4; k++) {
        float4 rr = __ldcs((const float4*)(r + tbase) + k);
        rv[4 * k + 0] = rr.x;
        rv[4 * k + 1] = rr.y;
        rv[4 * k + 2] = rr.z;
        rv[4 * k + 3] = rr.w;
    }

#pragma unroll
    for (int k = PER / 4 - 1; k >= 0; k--) {
        float4 w;
        {
            const float a = coeff(mask, 4 * k + 3);
            y = fmaf(a, y, rv[4 * k + 3]);
            w.w = (y - mean) * inv;
        }
        {
            const float a = coeff(mask, 4 * k + 2);
            y = fmaf(a, y, rv[4 * k + 2]);
            w.z = (y - mean) * inv;
        }
        {
            const float a = coeff(mask, 4 * k + 1);
            y = fmaf(a, y, rv[4 * k + 1]);
            w.y = (y - mean) * inv;
        }
        {
            const float a = coeff(mask, 4 * k + 0);
            y = fmaf(a, y, rv[4 * k + 0]);
            w.x = (y - mean) * inv;
        }
        __stcs((float4*)(o + tbase) + k, w);
    }
}

extern "C" void kernel_launch(void* const* d_in, const int* in_sizes, int n_in,
                              void* d_out, int out_size)
{
    const float* rewards = (const float*)d_in[0];
    const float* dones   = (const float*)d_in[1];
    float* out = (float*)d_out;

    const int n = in_sizes[0];
    const int B = n / T_LEN;

    scan_stats_kernel<<<B, THREADS_SCAN>>>(rewards, dones);
    mean_kernel<<<1, 256>>>(B);
    finalize_kernel<<<B, THREADS_SCAN>>>(rewards, out);
}

// round 14
// speedup vs baseline: 1.1416x; 1.0169x over previous
#include <cuda_runtime.h>
#include <math.h>

#define T_LEN 8192
#define THREADS_SCAN 1024
#define NWARPS (THREADS_SCAN / 32)       // 32
#define PER (T_LEN / THREADS_SCAN)       // 8 elements per thread
#define DISCOUNT_BITS 0x3F7D70A4u        // 0.99f
#define EPS 1e-9f
#define MAX_ROWS 4096                    // B = 4096 in this problem

__device__ float g_rowsum[MAX_ROWS];
__device__ float g_rowinv[MAX_ROWS];
__device__ float g_mean;
// Per-thread replay state: incoming carry + packed done mask (8 bits used)
__device__ float         g_carry[MAX_ROWS * THREADS_SCAN];   // 16 MB
__device__ unsigned char g_mask [MAX_ROWS * THREADS_SCAN];   //  4 MB

// Branchless coefficient: a_i = done_i ? 0.0f : 0.99f, no predicates.
__device__ __forceinline__ float coeff(unsigned mask, int i)
{
    const unsigned t = (unsigned)(((int)(mask << (31 - i))) >> 31);
    return __uint_as_float(DISCOUNT_BITS & ~t);
}

// ---------------------------------------------------------------------------
// P1: per-row reverse affine scan -> per-thread carry + per-row stats.
// ret[t] = r[t] + a[t]*ret[t+1],  a[t] = 0.99*(1-done[t]), done binary.
// Stats computed ALGEBRAICALLY during compose via prefix-map moments:
//   y_i = A_i*yin + B_i  =>  sum   = SA*yin + SB
//                            sumsq = SA2*yin^2 + 2*SAB*yin + SB2
// so rv[] dies at end of compose and there is no serial replay tail.
// ---------------------------------------------------------------------------
__global__ __launch_bounds__(THREADS_SCAN, 2)
void scan_stats_kernel(const float* __restrict__ rew,
                       const float* __restrict__ done)
{
    const int b = blockIdx.x;
    const size_t rowoff = (size_t)b * T_LEN;
    const float* r = rew + rowoff;
    const float* d = done + rowoff;

    const int j    = threadIdx.x;
    const int lane = j & 31;
    const int warp = j >> 5;
    const int tbase = T_LEN - PER * (j + 1);

    float rv[PER];
    unsigned mask = 0;   // bit i set -> done at local index i

#pragma unroll
    for (int k = 0; k < PER / 4; k++) {
        float4 rr = __ldcs((const float4*)(r + tbase) + k);
        float4 dd = __ldcs((const float4*)(d + tbase) + k);
        rv[4 * k + 0] = rr.x;
        rv[4 * k + 1] = rr.y;
        rv[4 * k + 2] = rr.z;
        rv[4 * k + 3] = rr.w;
        if (dd.x != 0.0f) mask |= (1u << (4 * k + 0));
        if (dd.y != 0.0f) mask |= (1u << (4 * k + 1));
        if (dd.z != 0.0f) mask |= (1u << (4 * k + 2));
        if (dd.w != 0.0f) mask |= (1u << (4 * k + 3));
    }

    // Compose map (t-descending) + moment accumulators.
    float A = 1.0f, B = 0.0f;
    float SA = 0.0f, SB = 0.0f, SA2 = 0.0f, SAB = 0.0f, SB2 = 0.0f;
#pragma unroll
    for (int i = PER - 1; i >= 0; i--) {
        const float a = coeff(mask, i);
        B = fmaf(a, B, rv[i]);
        A = a * A;
        SB += B;
        SA += A;
        SB2 = fmaf(B, B, SB2);
        SAB = fmaf(A, B, SAB);
        SA2 = fmaf(A, A, SA2);
    }

    // Intra-warp inclusive affine scan.
#pragma unroll
    for (int off = 1; off < 32; off <<= 1) {
        float a1 = __shfl_up_sync(0xffffffffu, A, off);
        float b1 = __shfl_up_sync(0xffffffffu, B, off);
        if (lane >= off) {
            B = fmaf(A, b1, B);
            A = A * a1;
        }
    }

    // Exclusive-within-warp map for this thread
    float Ae = __shfl_up_sync(0xffffffffu, A, 1);
    float Be = __shfl_up_sync(0xffffffffu, B, 1);
    if (lane == 0) { Ae = 1.0f; Be = 0.0f; }

    __shared__ float sWA[NWARPS];
    __shared__ float sWB[NWARPS];
    __shared__ float sWP[NWARPS];
    __shared__ float sRS[NWARPS];
    __shared__ float sRQ[NWARPS];

    if (lane == 31) { sWA[warp] = A; sWB[warp] = B; }
    __syncthreads();

    if (warp == 0) {
        float a  = sWA[lane];
        float bb = sWB[lane];
#pragma unroll
        for (int off = 1; off < 32; off <<= 1) {
            float a1 = __shfl_up_sync(0xffffffffu, a, off);
            float b1 = __shfl_up_sync(0xffffffffu, bb, off);
            if (lane >= off) {
                bb = fmaf(a, b1, bb);
                a = a * a1;
            }
        }
        sWP[lane] = bb;
    }
    __syncthreads();

    // Incoming value for this thread (row starts from y0 = 0)
    const float Bw = (warp == 0) ? 0.0f : sWP[warp - 1];
    const float yin = fmaf(Ae, Bw, Be);

    // Persist replay state for P2
    const size_t sidx = (size_t)b * THREADS_SCAN + j;
    g_carry[sidx] = yin;
    g_mask[sidx]  = (unsigned char)mask;

    // Closed-form chunk stats (2 fmas instead of an 8-step serial chain)
    float lsum = fmaf(SA, yin, SB);
    float lsq  = fmaf(yin, fmaf(SA2, yin, 2.0f * SAB), SB2);

    // Deterministic block reduction of sum / sumsq
#pragma unroll
    for (int off = 16; off > 0; off >>= 1) {
        lsum += __shfl_down_sync(0xffffffffu, lsum, off);
        lsq  += __shfl_down_sync(0xffffffffu, lsq,  off);
    }
    if (lane == 0) { sRS[warp] = lsum; sRQ[warp] = lsq; }
    __syncthreads();
    if (warp == 0) {
        float s = sRS[lane];
        float q = sRQ[lane];
#pragma unroll
        for (int off = 16; off > 0; off >>= 1) {
            s += __shfl_down_sync(0xffffffffu, s, off);
            q += __shfl_down_sync(0xffffffffu, q, off);
        }
        if (lane == 0) {
            g_rowsum[b] = s;
            float var = (q - s * s * (1.0f / T_LEN)) * (1.0f / (T_LEN - 1));
            var = fmaxf(var, 0.0f);
            g_rowinv[b] = 1.0f / (sqrtf(var) + EPS);
        }
    }
}

// ---------------------------------------------------------------------------
// K2: deterministic reduction of row sums -> global mean (256 thr, shuffle)
// ---------------------------------------------------------------------------
__global__ __launch_bounds__(256)
void mean_kernel(int n_rows)
{
    __shared__ double sd[8];
    const int j = threadIdx.x;
    const int lane = j & 31;
    const int warp = j >> 5;
    double acc = 0.0;
    for (int i = j; i < n_rows; i += 256)
        acc += (double)g_rowsum[i];
#pragma unroll
    for (int off = 16; off > 0; off >>= 1)
        acc += __shfl_down_sync(0xffffffffu, acc, off);
    if (lane == 0) sd[warp] = acc;
    __syncthreads();
    if (warp == 0) {
        double v = (lane < 8) ? sd[lane] : 0.0;
#pragma unroll
        for (int off = 4; off > 0; off >>= 1)
            v += __shfl_down_sync(0xffffffffu, v, off);
        if (lane == 0)
            g_mean = (float)(v / ((double)n_rows * (double)T_LEN));
    }
}

// ---------------------------------------------------------------------------
// P2: barrier-free replay + normalize + store.
// Reload rewards, carry, mask; replay the original fma chain from the stored
// carry (returns bit-identical to the scan's values); write
// (y - mean) * rowinv[b].
// ---------------------------------------------------------------------------
__global__ __launch_bounds__(THREADS_SCAN, 2)
void finalize_kernel(const float* __restrict__ rew,
                     float* __restrict__ out)
{
    const int b = blockIdx.x;
    const size_t rowoff = (size_t)b * T_LEN;
    const float* r = rew + rowoff;
    float* o = out + rowoff;

    const int j = threadIdx.x;
    const int tbase = T_LEN - PER * (j + 1);

    const size_t sidx = (size_t)b * THREADS_SCAN + j;
    float y = g_carry[sidx];
    const unsigned mask = g_mask[sidx];
    const float mean = g_mean;
    const float inv  = g_rowinv[b];

    float rv[PER];
#pragma unroll
    for (int k = 0; k < PER / 4; k++) {
        float4 rr = __ldcs((const float4*)(r + tbase) + k);
        rv[4 * k + 0] = rr.x;
        rv[4 * k + 1] = rr.y;
        rv[4 * k + 2] = rr.z;
        rv[4 * k + 3] = rr.w;
    }

#pragma unroll
    for (int k = PER / 4 - 1; k >= 0; k--) {
        float4 w;
        {
            const float a = coeff(mask, 4 * k + 3);
            y = fmaf(a, y, rv[4 * k + 3]);
            w.w = (y - mean) * inv;
        }
        {
            const float a = coeff(mask, 4 * k + 2);
            y = fmaf(a, y, rv[4 * k + 2]);
            w.z = (y - mean) * inv;
        }
        {
            const float a = coeff(mask, 4 * k + 1);
            y = fmaf(a, y, rv[4 * k + 1]);
            w.y = (y - mean) * inv;
        }
        {
            const float a = coeff(mask, 4 * k + 0);
            y = fmaf(a, y, rv[4 * k + 0]);
            w.x = (y - mean) * inv;
        }
        __stcs((float4*)(o + tbase) + k, w);
    }
}

extern "C" void kernel_launch(void* const* d_in, const int* in_sizes, int n_in,
                              void* d_out, int out_size)
{
    const float* rewards = (const float*)d_in[0];
    const float* dones   = (const float*)d_in[1];
    float* out = (float*)d_out;

    const int n = in_sizes[0];
    const int B = n / T_LEN;

    scan_stats_kernel<<<B, THREADS_SCAN>>>(rewards, dones);
    mean_kernel<<<1, 256>>>(B);
    finalize_kernel<<<B, THREADS_SCAN>>>(rewards, out);
}